// round 1
// baseline (speedup 1.0000x reference)
#include <cuda_runtime.h>
#include <math.h>

// ---------------------------------------------------------------------------
// GaborAutoencoder: encoder (4 fp32 GEMMs + ReLU) -> wavelet synthesis.
// Inputs (metadata order): x(4096*2*2048), W1(1024*4096), b1, W2(512*1024),
// b2, W3(256*512), b3, W4(160*256), b4. Output float (4096,2,2048).
// ---------------------------------------------------------------------------

__device__ float g_h1[4096 * 1024];
__device__ float g_h2[4096 * 512];
__device__ float g_h3[4096 * 256];
__device__ float g_p [4096 * 160];

// ---------------------------------------------------------------------------
// NT GEMM: C[m,n] = act( sum_k A[m,k]*W[n,k] + bias[n] )
// A: MxK row-major (K contiguous), W: NxK row-major (K contiguous).
// ---------------------------------------------------------------------------
template<int BM, int BN, int BK, int TM, int TN, bool RELU, bool GN>
__global__ __launch_bounds__((BM / TM) * (BN / TN))
void gemm_nt_kernel(const float* __restrict__ A, const float* __restrict__ W,
                    const float* __restrict__ bias, float* __restrict__ C,
                    int M, int N, int K)
{
    constexpr int NT = (BM / TM) * (BN / TN);
    __shared__ float As[BK][BM + 4];
    __shared__ float Bs[BK][BN + 4];

    const int bm = blockIdx.y * BM;
    const int bn = blockIdx.x * BN;
    const int tid = threadIdx.x;
    const int tr = tid / (BN / TN);
    const int tc = tid % (BN / TN);

    float acc[TM][TN];
#pragma unroll
    for (int i = 0; i < TM; i++)
#pragma unroll
        for (int j = 0; j < TN; j++) acc[i][j] = 0.f;

    for (int k0 = 0; k0 < K; k0 += BK) {
#pragma unroll
        for (int p = tid; p < BM * BK / 4; p += NT) {
            int row = p / (BK / 4);
            int kk  = (p % (BK / 4)) * 4;
            float4 v = *(const float4*)(A + (size_t)(bm + row) * K + (k0 + kk));
            As[kk + 0][row] = v.x; As[kk + 1][row] = v.y;
            As[kk + 2][row] = v.z; As[kk + 3][row] = v.w;
        }
#pragma unroll
        for (int p = tid; p < BN * BK / 4; p += NT) {
            int row = p / (BK / 4);
            int kk  = (p % (BK / 4)) * 4;
            float4 v = make_float4(0.f, 0.f, 0.f, 0.f);
            if (!GN || (bn + row) < N)
                v = *(const float4*)(W + (size_t)(bn + row) * K + (k0 + kk));
            Bs[kk + 0][row] = v.x; Bs[kk + 1][row] = v.y;
            Bs[kk + 2][row] = v.z; Bs[kk + 3][row] = v.w;
        }
        __syncthreads();

#pragma unroll
        for (int kk = 0; kk < BK; kk++) {
            float ar[TM], br[TN];
#pragma unroll
            for (int i = 0; i < TM; i += 4) {
                float4 v = *(const float4*)&As[kk][tr * TM + i];
                ar[i] = v.x; ar[i + 1] = v.y; ar[i + 2] = v.z; ar[i + 3] = v.w;
            }
#pragma unroll
            for (int j = 0; j < TN; j += 4) {
                float4 v = *(const float4*)&Bs[kk][tc * TN + j];
                br[j] = v.x; br[j + 1] = v.y; br[j + 2] = v.z; br[j + 3] = v.w;
            }
#pragma unroll
            for (int i = 0; i < TM; i++)
#pragma unroll
                for (int j = 0; j < TN; j++)
                    acc[i][j] = fmaf(ar[i], br[j], acc[i][j]);
        }
        __syncthreads();
    }

    float bv[TN];
#pragma unroll
    for (int j = 0; j < TN; j += 4) {
        int c0 = bn + tc * TN + j;
        float4 v = make_float4(0.f, 0.f, 0.f, 0.f);
        if (!GN || c0 < N) v = *(const float4*)(bias + c0);
        bv[j] = v.x; bv[j + 1] = v.y; bv[j + 2] = v.z; bv[j + 3] = v.w;
    }
#pragma unroll
    for (int i = 0; i < TM; i++) {
        size_t row = (size_t)(bm + tr * TM + i);
#pragma unroll
        for (int j = 0; j < TN; j += 4) {
            int c0 = bn + tc * TN + j;
            if (GN && c0 >= N) continue;
            float4 v;
            v.x = acc[i][j + 0] + bv[j + 0];
            v.y = acc[i][j + 1] + bv[j + 1];
            v.z = acc[i][j + 2] + bv[j + 2];
            v.w = acc[i][j + 3] + bv[j + 3];
            if (RELU) {
                v.x = fmaxf(v.x, 0.f); v.y = fmaxf(v.y, 0.f);
                v.z = fmaxf(v.z, 0.f); v.w = fmaxf(v.w, 0.f);
            }
            *(float4*)(C + row * N + c0) = v;
        }
    }
}

// ---------------------------------------------------------------------------
// Wavelet synthesis.
// Block: 128 threads handle 8 batch elements; each thread owns a 128-sample
// chunk (16 threads per batch element). Per wavelet: exact start point
// (fp64 phase, fp32 exp/sincos) then multiplicative Gaussian recurrence +
// rotation recurrence. SMEM accumulator swizzled for conflict-free access.
// ---------------------------------------------------------------------------
#define SYNTH_SMEM (8 * 2048 * 4 + 8 * 32 * 6 * 4 + 8 * 32 * 3 * 8)

__global__ __launch_bounds__(128)
void synth_kernel(const float* __restrict__ P, float* __restrict__ out)
{
    extern __shared__ float sm[];
    float*  acc = sm;                       // 8*2048 floats, swizzled [i][col]
    float*  fp  = sm + 8 * 2048;            // [8*32][6]: A,i2s2,cosw,sinw,r,t0
    double* dp  = (double*)(fp + 8 * 32 * 6); // [8*32][3]: t0, w, phi

    const int tid = threadIdx.x;
    const int b0  = blockIdx.x * 8;

    // zero accumulator
    float4 z4 = make_float4(0.f, 0.f, 0.f, 0.f);
#pragma unroll
    for (int i = tid; i < 8 * 2048 / 4; i += 128)
        ((float4*)acc)[i] = z4;

    // derive per-(b,wavelet) params (fp64 for accuracy; cost is negligible)
    for (int p = tid; p < 8 * 32; p += 128) {
        int bl = p >> 5, n = p & 31;
        const float* q = P + (size_t)(b0 + bl) * 160 + n * 5;
        float  a  = q[0];
        double t0 = (1.0 / (1.0 + exp(-(double)q[1]))) * 2048.0;
        double fd = (1.0 / (1.0 + exp(-(double)q[2]))) * 0.5;
        double wd = 6.283185307179586 * fd;
        double sg = (1.0 / (1.0 + exp(-(double)q[3]))) * 200.0 + 2.0;
        double i2 = 1.0 / (2.0 * sg * sg);
        float* f6 = fp + p * 6;
        f6[0] = a;
        f6[1] = (float)i2;
        f6[2] = (float)cos(wd);
        f6[3] = (float)sin(wd);
        f6[4] = (float)exp(-2.0 * i2);
        f6[5] = (float)t0;
        double* d3 = dp + p * 3;
        d3[0] = t0; d3[1] = wd; d3[2] = (double)q[4];
    }
    __syncthreads();

    const int bl  = tid >> 4;
    const int tl  = tid & 15;
    const int col = tid;              // bl*16 + tl
    const int   sI = tl * 128;
    const float lo = (float)sI;
    const float hi = lo + 127.f;

    for (int n = 0; n < 32; n++) {
        const float* f6 = fp + (bl * 32 + n) * 6;
        float A = f6[0], i2 = f6[1], cw = f6[2], sw = f6[3], r = f6[4], t0f = f6[5];

        // skip if the Gaussian is negligible over this whole chunk
        float dn = fmaxf(fmaxf(lo - t0f, t0f - hi), 0.f);
        if (dn * dn * i2 > 18.f) continue;

        float dfar = fmaxf(fabsf(lo - t0f), fabsf(hi - t0f));
        const double* d3 = dp + (bl * 32 + n) * 3;
        double t0d = d3[0], wd = d3[1], phid = d3[2];
        double dtd = (double)sI - t0d;

        if (dfar * dfar * i2 < 55.f) {
            // ---- recurrence path ----
            double i2d = (double)i2;
            float g = A * __expf((float)(-dtd * dtd * i2d));
            float u = __expf((float)(-i2d * (2.0 * dtd + 1.0)));
            double ph = fma(wd, dtd, phid);
            double kq = rint(ph * 0.15915494309189535);
            float phr = (float)(ph - kq * 6.283185307179586);
            float c, s;
            __sincosf(phr, &s, &c);
#pragma unroll 4
            for (int i = 0; i < 128; i++) {
                int idx = i * 128 + ((col + i) & 127);
                acc[idx] += g * c;
                float cn  = fmaf(c, cw, -s * sw);
                float snn = fmaf(s, cw,  c * sw);
                c = cn; s = snn;
                g *= u;
                u *= r;
            }
        } else {
            // ---- exact path (tiny sigma: avoids under/overflow in ratios) ----
            for (int i = 0; i < 128; i++) {
                double dd = dtd + (double)i;
                float dt = (float)dd;
                float e = -dt * dt * i2;
                if (e > -18.f) {
                    double ph = fma(wd, dd, phid);
                    double kq = rint(ph * 0.15915494309189535);
                    float phr = (float)(ph - kq * 6.283185307179586);
                    int idx = i * 128 + ((col + i) & 127);
                    acc[idx] += A * __expf(e) * __cosf(phr);
                }
            }
        }
    }
    __syncthreads();

    // coalesced writeout, both channels identical
    for (int e = tid; e < 8 * 2048 / 4; e += 128) {
        int bl2 = e >> 9;            // 512 float4-groups per batch element
        int t   = (e & 511) * 4;
        int i0  = t & 127;
        int cb  = bl2 * 16 + (t >> 7);
        float4 v;
        v.x = acc[(i0 + 0) * 128 + ((cb + i0 + 0) & 127)];
        v.y = acc[(i0 + 1) * 128 + ((cb + i0 + 1) & 127)];
        v.z = acc[(i0 + 2) * 128 + ((cb + i0 + 2) & 127)];
        v.w = acc[(i0 + 3) * 128 + ((cb + i0 + 3) & 127)];
        size_t ob = ((size_t)(b0 + bl2) * 2) * 2048 + t;
        *(float4*)(out + ob)        = v;
        *(float4*)(out + ob + 2048) = v;
    }
}

// ---------------------------------------------------------------------------
extern "C" void kernel_launch(void* const* d_in, const int* in_sizes, int n_in,
                              void* d_out, int out_size)
{
    const float* x  = (const float*)d_in[0];
    const float* W1 = (const float*)d_in[1];
    const float* b1 = (const float*)d_in[2];
    const float* W2 = (const float*)d_in[3];
    const float* b2 = (const float*)d_in[4];
    const float* W3 = (const float*)d_in[5];
    const float* b3 = (const float*)d_in[6];
    const float* W4 = (const float*)d_in[7];
    const float* b4 = (const float*)d_in[8];
    float* out = (float*)d_out;

    float *h1, *h2, *h3, *pp;
    cudaGetSymbolAddress((void**)&h1, g_h1);
    cudaGetSymbolAddress((void**)&h2, g_h2);
    cudaGetSymbolAddress((void**)&h3, g_h3);
    cudaGetSymbolAddress((void**)&pp, g_p);

    // L1: (4096x4096) @ W1^T -> (4096x1024), ReLU
    {
        dim3 grid(1024 / 128, 4096 / 128);
        gemm_nt_kernel<128, 128, 16, 8, 8, true, false><<<grid, 256>>>(
            x, W1, b1, h1, 4096, 1024, 4096);
    }
    // L2: -> (4096x512), ReLU
    {
        dim3 grid(512 / 128, 4096 / 128);
        gemm_nt_kernel<128, 128, 16, 8, 8, true, false><<<grid, 256>>>(
            h1, W2, b2, h2, 4096, 512, 1024);
    }
    // L3: -> (4096x256), ReLU
    {
        dim3 grid(256 / 64, 4096 / 64);
        gemm_nt_kernel<64, 64, 16, 4, 4, true, false><<<grid, 256>>>(
            h2, W3, b3, h3, 4096, 256, 512);
    }
    // L4: -> (4096x160), linear
    {
        dim3 grid((160 + 63) / 64, 4096 / 64);
        gemm_nt_kernel<64, 64, 16, 4, 4, false, true><<<grid, 256>>>(
            h3, W4, b4, pp, 4096, 160, 256);
    }
    // Synthesis
    cudaFuncSetAttribute(synth_kernel,
                         cudaFuncAttributeMaxDynamicSharedMemorySize,
                         SYNTH_SMEM);
    synth_kernel<<<4096 / 8, 128, SYNTH_SMEM>>>(pp, out);
}